// round 4
// baseline (speedup 1.0000x reference)
#include <cuda_runtime.h>
#include <math.h>

#define Dq 256
#define Mq 512
#define RB 32
#define NT 512
#define NROWS (32*4096)

// Padded k-major smem strides (floats). 36 keeps float4 alignment AND spreads banks.
#define WS_STRIDE 36
#define MS_STRIDE 36

// SMEM float offsets
#define XS_OFF   0                       // xsT [256][32]   k-major
#define WS_OFF   (XS_OFF + Dq*RB)        // wsT [512][36]   k-major padded
#define MS_OFF   (WS_OFF + Mq*WS_STRIDE) // msT [256][36]   k-major padded
#define R1_OFF   (MS_OFF + Dq*MS_STRIDE) // pmax [16][32]
#define R2_OFF   (R1_OFF + 512)          // psum [16][32]
#define SMEM_FLOATS (R2_OFF + 512)

// Pre-transposed operands (built by vm_prep; L2-resident, 1.5MB total with memv).
__device__ float g_memT[Dq*Mq];   // [k][m]  = memory[m][k]
__device__ float g_WgT[2*Dq*Dq];  // [dc][e] = Wg[e][dc]

typedef unsigned long long u64;

__device__ __forceinline__ u64 bcast2(float v){
    u64 r; asm("mov.b64 %0, {%1, %1};" : "=l"(r) : "f"(v)); return r;
}
__device__ __forceinline__ void unpack2(u64 v, float& lo, float& hi){
    asm("mov.b64 {%0, %1}, %2;" : "=f"(lo), "=f"(hi) : "l"(v));
}
// Packed fp32x2 FMA
__device__ __forceinline__ void ffma2(u64& d, u64 a, u64 b){
    asm("fma.rn.f32x2 %0, %1, %2, %0;" : "+l"(d) : "l"(a), "l"(b));
}

__global__ void vm_prep(const float* __restrict__ mem, const float* __restrict__ wg){
    int idx = blockIdx.x*blockDim.x + threadIdx.x;
    if (idx < Mq*Dq){
        int m = idx >> 8, k = idx & 255;      // memory: [512][256]
        g_memT[k*Mq + m] = mem[idx];
        int e = idx >> 9, dc = idx & 511;     // Wg: [256][512]
        g_WgT[dc*Dq + e] = wg[idx];
    }
}

__global__ __launch_bounds__(NT, 1)
void vm_fused(const float* __restrict__ x,
              const float* __restrict__ memv,
              const float* __restrict__ bg,
              float* __restrict__ out_enh,
              float* __restrict__ out_w)
{
    extern __shared__ float smem[];
    float* xsT = smem + XS_OFF;   // [k][32]
    float* wsT = smem + WS_OFF;   // [k][36]
    float* msT = smem + MS_OFF;   // [k][36]
    float* red1 = smem + R1_OFF;
    float* red2 = smem + R2_OFF;

    const int tid = threadIdx.x;
    const int rowbase = blockIdx.x * RB;
    const int wid = tid >> 5, lane = tid & 31;

    // warp tiling: rb selects 16-row half, cb selects column block
    const int rb = wid >> 3;           // 0..1
    const int cb = wid & 7;            // 0..7
    const int g  = lane >> 3;          // 0..3  row-quad within half
    const int o  = lane & 7;           // 0..7  col-quad
    const int r0 = rb*16 + g*4;        // 4 contiguous rows per lane

    // ---------------- Phase A: x block -> xsT[k][r] (k-major) --------------
    {
        int r  = lane;
        #pragma unroll
        for (int cc = 0; cc < 4; cc++){
            int c4 = wid + cc*16;       // 0..63 float4-chunks of the row
            float4 v = *(const float4*)(x + (size_t)(rowbase + r)*Dq + c4*4);
            xsT[(c4*4+0)*RB + r] = v.x;
            xsT[(c4*4+1)*RB + r] = v.y;
            xsT[(c4*4+2)*RB + r] = v.z;
            xsT[(c4*4+3)*RB + r] = v.w;
        }
    }
    __syncthreads();

    // ---------------- Phase B: logits[32x512] = x @ memory^T ---------------
    // warp: 16 rows x 64 cols. lane: 4 rows x 8 cols (two coalesced 4-col strips).
    {
        const int c0 = cb*64 + o*4;          // strip 1
        const int c1 = c0 + 32;              // strip 2
        u64 acc[4][4];
        #pragma unroll
        for (int i=0;i<4;i++){ acc[i][0]=0; acc[i][1]=0; acc[i][2]=0; acc[i][3]=0; }

        #pragma unroll 4
        for (int k=0;k<Dq;k++){
            float4 av = *(const float4*)(xsT + k*RB + r0);                 // 1 wf LDS
            ulonglong2 B0 = *(const ulonglong2*)(g_memT + k*Mq + c0);      // 128B coalesced
            ulonglong2 B1 = *(const ulonglong2*)(g_memT + k*Mq + c1);      // 128B coalesced
            u64 a;
            a = bcast2(av.x); ffma2(acc[0][0],a,B0.x); ffma2(acc[0][1],a,B0.y); ffma2(acc[0][2],a,B1.x); ffma2(acc[0][3],a,B1.y);
            a = bcast2(av.y); ffma2(acc[1][0],a,B0.x); ffma2(acc[1][1],a,B0.y); ffma2(acc[1][2],a,B1.x); ffma2(acc[1][3],a,B1.y);
            a = bcast2(av.z); ffma2(acc[2][0],a,B0.x); ffma2(acc[2][1],a,B0.y); ffma2(acc[2][2],a,B1.x); ffma2(acc[2][3],a,B1.y);
            a = bcast2(av.w); ffma2(acc[3][0],a,B0.x); ffma2(acc[3][1],a,B0.y); ffma2(acc[3][2],a,B1.x); ffma2(acc[3][3],a,B1.y);
        }
        // transpose 4x8 in regs, store column-major float4s into wsT[k][r]
        float s[4][8];
        #pragma unroll
        for (int i=0;i<4;i++){
            unpack2(acc[i][0], s[i][0], s[i][1]);
            unpack2(acc[i][1], s[i][2], s[i][3]);
            unpack2(acc[i][2], s[i][4], s[i][5]);
            unpack2(acc[i][3], s[i][6], s[i][7]);
        }
        #pragma unroll
        for (int cc=0; cc<8; cc++){
            int col = (cc<4) ? (c0+cc) : (c1+cc-4);
            float4 v; v.x=s[0][cc]; v.y=s[1][cc]; v.z=s[2][cc]; v.w=s[3][cc];
            *(float4*)(wsT + col*WS_STRIDE + r0) = v;
        }
    }
    __syncthreads();

    // ---------------- Phase C: softmax over k (512) per row ---------------
    // warp w owns k-block [w*32, w*32+32); lane = row. All accesses conflict-free.
    {
        const int k0 = wid*32;
        float v[32];
        float mx = -3.402823466e38f;
        #pragma unroll
        for (int j=0;j<32;j++){ v[j] = wsT[(k0+j)*WS_STRIDE + lane]; mx = fmaxf(mx, v[j]); }
        red1[wid*32 + lane] = mx;
        __syncthreads();
        float rm = -3.402823466e38f;
        #pragma unroll
        for (int i=0;i<16;i++) rm = fmaxf(rm, red1[i*32 + lane]);
        float sm = 0.f;
        #pragma unroll
        for (int j=0;j<32;j++){ v[j] = __expf(v[j]-rm); sm += v[j]; }
        red2[wid*32 + lane] = sm;
        __syncthreads();
        float rs = 0.f;
        #pragma unroll
        for (int i=0;i<16;i++) rs += red2[i*32 + lane];
        float inv = 1.f / rs;
        #pragma unroll
        for (int j=0;j<32;j++) wsT[(k0+j)*WS_STRIDE + lane] = v[j]*inv;
        __syncthreads();
        // coalesced out_w writeout (warp = 2 rows, lanes span k)
        #pragma unroll
        for (int rr=0; rr<2; rr++){
            int r = wid*2 + rr;
            float* wout = out_w + (size_t)(rowbase + r)*Mq;
            #pragma unroll
            for (int t=0;t<16;t++)
                wout[lane + 32*t] = wsT[(lane + 32*t)*WS_STRIDE + r];
        }
    }

    // ---------------- Phase D: mr[32x256] = w @ memory ---------------------
    // warp: 16 rows x 32 cols. lane: 4 rows x 4 cols (contiguous).
    {
        const int c0 = cb*32 + o*4;
        u64 acc[4][2];
        #pragma unroll
        for (int i=0;i<4;i++){ acc[i][0]=0; acc[i][1]=0; }
        #pragma unroll 4
        for (int k=0;k<Mq;k++){
            float4 av = *(const float4*)(wsT + k*WS_STRIDE + r0);          // 1 wf LDS
            ulonglong2 Bv = *(const ulonglong2*)(memv + k*Dq + c0);        // 128B coalesced
            u64 a;
            a = bcast2(av.x); ffma2(acc[0][0],a,Bv.x); ffma2(acc[0][1],a,Bv.y);
            a = bcast2(av.y); ffma2(acc[1][0],a,Bv.x); ffma2(acc[1][1],a,Bv.y);
            a = bcast2(av.z); ffma2(acc[2][0],a,Bv.x); ffma2(acc[2][1],a,Bv.y);
            a = bcast2(av.w); ffma2(acc[3][0],a,Bv.x); ffma2(acc[3][1],a,Bv.y);
        }
        float m[4][4];
        #pragma unroll
        for (int i=0;i<4;i++){
            unpack2(acc[i][0], m[i][0], m[i][1]);
            unpack2(acc[i][1], m[i][2], m[i][3]);
        }
        #pragma unroll
        for (int cc=0; cc<4; cc++){
            float4 v; v.x=m[0][cc]; v.y=m[1][cc]; v.z=m[2][cc]; v.w=m[3][cc];
            *(float4*)(msT + (c0+cc)*MS_STRIDE + r0) = v;
        }
    }
    __syncthreads();

    // ---------------- Phase E: gate + blend --------------------------------
    // warp: 16 rows x 32 e-cols. lane: 4 rows x 4 cols.
    {
        const int e0 = cb*32 + o*4;
        u64 acc[4][2];
        #pragma unroll
        for (int i=0;i<4;i++){ acc[i][0]=0; acc[i][1]=0; }
        #pragma unroll 4
        for (int k=0;k<Dq;k++){
            float4 xa = *(const float4*)(xsT + k*RB + r0);
            float4 ma = *(const float4*)(msT + k*MS_STRIDE + r0);
            ulonglong2 B1 = *(const ulonglong2*)(g_WgT + (size_t)k*Dq + e0);
            ulonglong2 B2 = *(const ulonglong2*)(g_WgT + (size_t)(Dq+k)*Dq + e0);
            u64 a;
            a = bcast2(xa.x); ffma2(acc[0][0],a,B1.x); ffma2(acc[0][1],a,B1.y);
            a = bcast2(ma.x); ffma2(acc[0][0],a,B2.x); ffma2(acc[0][1],a,B2.y);
            a = bcast2(xa.y); ffma2(acc[1][0],a,B1.x); ffma2(acc[1][1],a,B1.y);
            a = bcast2(ma.y); ffma2(acc[1][0],a,B2.x); ffma2(acc[1][1],a,B2.y);
            a = bcast2(xa.z); ffma2(acc[2][0],a,B1.x); ffma2(acc[2][1],a,B1.y);
            a = bcast2(ma.z); ffma2(acc[2][0],a,B2.x); ffma2(acc[2][1],a,B2.y);
            a = bcast2(xa.w); ffma2(acc[3][0],a,B1.x); ffma2(acc[3][1],a,B1.y);
            a = bcast2(ma.w); ffma2(acc[3][0],a,B2.x); ffma2(acc[3][1],a,B2.y);
        }
        // epilogue: gather x and mr column-vectors, sigmoid, blend, store
        float4 bgv = *(const float4*)(bg + e0);
        float xv[4][4], mv[4][4];
        #pragma unroll
        for (int j=0;j<4;j++){
            float4 xc = *(const float4*)(xsT + (e0+j)*RB + r0);
            float4 mc = *(const float4*)(msT + (e0+j)*MS_STRIDE + r0);
            xv[j][0]=xc.x; xv[j][1]=xc.y; xv[j][2]=xc.z; xv[j][3]=xc.w;
            mv[j][0]=mc.x; mv[j][1]=mc.y; mv[j][2]=mc.z; mv[j][3]=mc.w;
        }
        #pragma unroll
        for (int i=0;i<4;i++){
            float p0,p1,p2,p3;
            unpack2(acc[i][0], p0, p1);
            unpack2(acc[i][1], p2, p3);
            p0 += bgv.x; p1 += bgv.y; p2 += bgv.z; p3 += bgv.w;
            float g0 = 1.f/(1.f+__expf(-p0));
            float g1 = 1.f/(1.f+__expf(-p1));
            float g2 = 1.f/(1.f+__expf(-p2));
            float g3 = 1.f/(1.f+__expf(-p3));
            float4 ov;
            ov.x = xv[0][i] + g0*mv[0][i];
            ov.y = xv[1][i] + g1*mv[1][i];
            ov.z = xv[2][i] + g2*mv[2][i];
            ov.w = xv[3][i] + g3*mv[3][i];
            *(float4*)(out_enh + (size_t)(rowbase + r0 + i)*Dq + e0) = ov;
        }
    }
}

extern "C" void kernel_launch(void* const* d_in, const int* in_sizes, int n_in,
                              void* d_out, int out_size)
{
    const float* x    = (const float*)d_in[0];
    const float* memv = (const float*)d_in[1];
    const float* wg   = (const float*)d_in[2];
    const float* bg   = (const float*)d_in[3];

    float* out_enh = (float*)d_out;                       // (B,S,D) first
    float* out_w   = out_enh + (size_t)NROWS * Dq;        // then (B,S,M)

    const size_t smem_bytes = (size_t)SMEM_FLOATS * sizeof(float);  // ~144 KB
    cudaFuncSetAttribute(vm_fused, cudaFuncAttributeMaxDynamicSharedMemorySize, (int)smem_bytes);

    vm_prep<<<(Mq*Dq + 255)/256, 256>>>(memv, wg);
    vm_fused<<<NROWS/RB, NT, smem_bytes>>>(x, memv, bg, out_enh, out_w);
}

// round 5
// speedup vs baseline: 1.0019x; 1.0019x over previous
#include <cuda_runtime.h>
#include <math.h>

#define Dq 256
#define Mq 512
#define RB 32
#define NT 512
#define NROWS (32*4096)

// Padded k-major smem strides (floats). 36 keeps float4 alignment AND spreads banks.
#define WS_STRIDE 36
#define MS_STRIDE 36

// SMEM float offsets
#define XS_OFF   0                       // xsT [256][32]   k-major
#define WS_OFF   (XS_OFF + Dq*RB)        // wsT [512][36]   k-major padded
#define MS_OFF   (WS_OFF + Mq*WS_STRIDE) // msT [256][36]   k-major padded
#define R1_OFF   (MS_OFF + Dq*MS_STRIDE) // pmax [16][32]
#define R2_OFF   (R1_OFF + 512)          // psum [16][32]
#define SMEM_FLOATS (R2_OFF + 512)

// Pre-transposed operands (built by vm_prep; L2-resident, 1.5MB total with memv).
__device__ float g_memT[Dq*Mq];   // [k][m]  = memory[m][k]
__device__ float g_WgT[2*Dq*Dq];  // [dc][e] = Wg[e][dc]

typedef unsigned long long u64;

__device__ __forceinline__ u64 bcast2(float v){
    u64 r; asm("mov.b64 %0, {%1, %1};" : "=l"(r) : "f"(v)); return r;
}
__device__ __forceinline__ void unpack2(u64 v, float& lo, float& hi){
    asm("mov.b64 {%0, %1}, %2;" : "=f"(lo), "=f"(hi) : "l"(v));
}
// Packed fp32x2 FMA
__device__ __forceinline__ void ffma2(u64& d, u64 a, u64 b){
    asm("fma.rn.f32x2 %0, %1, %2, %0;" : "+l"(d) : "l"(a), "l"(b));
}

__global__ void vm_prep(const float* __restrict__ mem, const float* __restrict__ wg){
    int idx = blockIdx.x*blockDim.x + threadIdx.x;
    if (idx < Mq*Dq){
        int m = idx >> 8, k = idx & 255;      // memory: [512][256]
        g_memT[k*Mq + m] = mem[idx];
        int e = idx >> 9, dc = idx & 511;     // Wg: [256][512]
        g_WgT[dc*Dq + e] = wg[idx];
    }
}

__global__ __launch_bounds__(NT, 1)
void vm_fused(const float* __restrict__ x,
              const float* __restrict__ memv,
              const float* __restrict__ bg,
              float* __restrict__ out_enh,
              float* __restrict__ out_w)
{
    extern __shared__ float smem[];
    float* xsT = smem + XS_OFF;   // [k][32]
    float* wsT = smem + WS_OFF;   // [k][36]
    float* msT = smem + MS_OFF;   // [k][36]
    float* red1 = smem + R1_OFF;
    float* red2 = smem + R2_OFF;

    const int tid = threadIdx.x;
    const int rowbase = blockIdx.x * RB;
    const int wid = tid >> 5, lane = tid & 31;

    // warp tiling: rb selects 16-row half, cb selects column block
    const int rb = wid >> 3;           // 0..1
    const int cb = wid & 7;            // 0..7
    const int g  = lane >> 3;          // 0..3  row-quad within half
    const int o  = lane & 7;           // 0..7  col-quad
    const int r0 = rb*16 + g*4;        // 4 contiguous rows per lane

    // ---------------- Phase A: x block -> xsT[k][r] (k-major) --------------
    {
        int r  = lane;
        #pragma unroll
        for (int cc = 0; cc < 4; cc++){
            int c4 = wid + cc*16;       // 0..63 float4-chunks of the row
            float4 v = *(const float4*)(x + (size_t)(rowbase + r)*Dq + c4*4);
            xsT[(c4*4+0)*RB + r] = v.x;
            xsT[(c4*4+1)*RB + r] = v.y;
            xsT[(c4*4+2)*RB + r] = v.z;
            xsT[(c4*4+3)*RB + r] = v.w;
        }
    }
    __syncthreads();

    // ---------------- Phase B: logits[32x512] = x @ memory^T ---------------
    // warp: 16 rows x 64 cols. lane: 4 rows x 8 cols (two coalesced 4-col strips).
    {
        const int c0 = cb*64 + o*4;          // strip 1
        const int c1 = c0 + 32;              // strip 2
        u64 acc[4][4];
        #pragma unroll
        for (int i=0;i<4;i++){ acc[i][0]=0; acc[i][1]=0; acc[i][2]=0; acc[i][3]=0; }

        #pragma unroll 4
        for (int k=0;k<Dq;k++){
            float4 av = *(const float4*)(xsT + k*RB + r0);                 // 1 wf LDS
            ulonglong2 B0 = *(const ulonglong2*)(g_memT + k*Mq + c0);      // 128B coalesced
            ulonglong2 B1 = *(const ulonglong2*)(g_memT + k*Mq + c1);      // 128B coalesced
            u64 a;
            a = bcast2(av.x); ffma2(acc[0][0],a,B0.x); ffma2(acc[0][1],a,B0.y); ffma2(acc[0][2],a,B1.x); ffma2(acc[0][3],a,B1.y);
            a = bcast2(av.y); ffma2(acc[1][0],a,B0.x); ffma2(acc[1][1],a,B0.y); ffma2(acc[1][2],a,B1.x); ffma2(acc[1][3],a,B1.y);
            a = bcast2(av.z); ffma2(acc[2][0],a,B0.x); ffma2(acc[2][1],a,B0.y); ffma2(acc[2][2],a,B1.x); ffma2(acc[2][3],a,B1.y);
            a = bcast2(av.w); ffma2(acc[3][0],a,B0.x); ffma2(acc[3][1],a,B0.y); ffma2(acc[3][2],a,B1.x); ffma2(acc[3][3],a,B1.y);
        }
        // transpose 4x8 in regs, store column-major float4s into wsT[k][r]
        float s[4][8];
        #pragma unroll
        for (int i=0;i<4;i++){
            unpack2(acc[i][0], s[i][0], s[i][1]);
            unpack2(acc[i][1], s[i][2], s[i][3]);
            unpack2(acc[i][2], s[i][4], s[i][5]);
            unpack2(acc[i][3], s[i][6], s[i][7]);
        }
        #pragma unroll
        for (int cc=0; cc<8; cc++){
            int col = (cc<4) ? (c0+cc) : (c1+cc-4);
            float4 v; v.x=s[0][cc]; v.y=s[1][cc]; v.z=s[2][cc]; v.w=s[3][cc];
            *(float4*)(wsT + col*WS_STRIDE + r0) = v;
        }
    }
    __syncthreads();

    // ---------------- Phase C: softmax over k (512) per row ---------------
    // warp w owns k-block [w*32, w*32+32); lane = row. All accesses conflict-free.
    {
        const int k0 = wid*32;
        float v[32];
        float mx = -3.402823466e38f;
        #pragma unroll
        for (int j=0;j<32;j++){ v[j] = wsT[(k0+j)*WS_STRIDE + lane]; mx = fmaxf(mx, v[j]); }
        red1[wid*32 + lane] = mx;
        __syncthreads();
        float rm = -3.402823466e38f;
        #pragma unroll
        for (int i=0;i<16;i++) rm = fmaxf(rm, red1[i*32 + lane]);
        float sm = 0.f;
        #pragma unroll
        for (int j=0;j<32;j++){ v[j] = __expf(v[j]-rm); sm += v[j]; }
        red2[wid*32 + lane] = sm;
        __syncthreads();
        float rs = 0.f;
        #pragma unroll
        for (int i=0;i<16;i++) rs += red2[i*32 + lane];
        float inv = 1.f / rs;
        #pragma unroll
        for (int j=0;j<32;j++) wsT[(k0+j)*WS_STRIDE + lane] = v[j]*inv;
        __syncthreads();
        // coalesced out_w writeout (warp = 2 rows, lanes span k)
        #pragma unroll
        for (int rr=0; rr<2; rr++){
            int r = wid*2 + rr;
            float* wout = out_w + (size_t)(rowbase + r)*Mq;
            #pragma unroll
            for (int t=0;t<16;t++)
                wout[lane + 32*t] = wsT[(lane + 32*t)*WS_STRIDE + r];
        }
    }

    // ---------------- Phase D: mr[32x256] = w @ memory ---------------------
    // warp: 16 rows x 32 cols. lane: 4 rows x 4 cols (contiguous).
    {
        const int c0 = cb*32 + o*4;
        u64 acc[4][2];
        #pragma unroll
        for (int i=0;i<4;i++){ acc[i][0]=0; acc[i][1]=0; }
        #pragma unroll 4
        for (int k=0;k<Mq;k++){
            float4 av = *(const float4*)(wsT + k*WS_STRIDE + r0);          // 1 wf LDS
            ulonglong2 Bv = *(const ulonglong2*)(memv + k*Dq + c0);        // 128B coalesced
            u64 a;
            a = bcast2(av.x); ffma2(acc[0][0],a,Bv.x); ffma2(acc[0][1],a,Bv.y);
            a = bcast2(av.y); ffma2(acc[1][0],a,Bv.x); ffma2(acc[1][1],a,Bv.y);
            a = bcast2(av.z); ffma2(acc[2][0],a,Bv.x); ffma2(acc[2][1],a,Bv.y);
            a = bcast2(av.w); ffma2(acc[3][0],a,Bv.x); ffma2(acc[3][1],a,Bv.y);
        }
        float m[4][4];
        #pragma unroll
        for (int i=0;i<4;i++){
            unpack2(acc[i][0], m[i][0], m[i][1]);
            unpack2(acc[i][1], m[i][2], m[i][3]);
        }
        #pragma unroll
        for (int cc=0; cc<4; cc++){
            float4 v; v.x=m[0][cc]; v.y=m[1][cc]; v.z=m[2][cc]; v.w=m[3][cc];
            *(float4*)(msT + (c0+cc)*MS_STRIDE + r0) = v;
        }
    }
    __syncthreads();

    // ---------------- Phase E: gate + blend --------------------------------
    // warp: 16 rows x 32 e-cols. lane: 4 rows x 4 cols.
    {
        const int e0 = cb*32 + o*4;
        u64 acc[4][2];
        #pragma unroll
        for (int i=0;i<4;i++){ acc[i][0]=0; acc[i][1]=0; }
        #pragma unroll 4
        for (int k=0;k<Dq;k++){
            float4 xa = *(const float4*)(xsT + k*RB + r0);
            float4 ma = *(const float4*)(msT + k*MS_STRIDE + r0);
            ulonglong2 B1 = *(const ulonglong2*)(g_WgT + (size_t)k*Dq + e0);
            ulonglong2 B2 = *(const ulonglong2*)(g_WgT + (size_t)(Dq+k)*Dq + e0);
            u64 a;
            a = bcast2(xa.x); ffma2(acc[0][0],a,B1.x); ffma2(acc[0][1],a,B1.y);
            a = bcast2(ma.x); ffma2(acc[0][0],a,B2.x); ffma2(acc[0][1],a,B2.y);
            a = bcast2(xa.y); ffma2(acc[1][0],a,B1.x); ffma2(acc[1][1],a,B1.y);
            a = bcast2(ma.y); ffma2(acc[1][0],a,B2.x); ffma2(acc[1][1],a,B2.y);
            a = bcast2(xa.z); ffma2(acc[2][0],a,B1.x); ffma2(acc[2][1],a,B1.y);
            a = bcast2(ma.z); ffma2(acc[2][0],a,B2.x); ffma2(acc[2][1],a,B2.y);
            a = bcast2(xa.w); ffma2(acc[3][0],a,B1.x); ffma2(acc[3][1],a,B1.y);
            a = bcast2(ma.w); ffma2(acc[3][0],a,B2.x); ffma2(acc[3][1],a,B2.y);
        }
        // epilogue: gather x and mr column-vectors, sigmoid, blend, store
        float4 bgv = *(const float4*)(bg + e0);
        float xv[4][4], mv[4][4];
        #pragma unroll
        for (int j=0;j<4;j++){
            float4 xc = *(const float4*)(xsT + (e0+j)*RB + r0);
            float4 mc = *(const float4*)(msT + (e0+j)*MS_STRIDE + r0);
            xv[j][0]=xc.x; xv[j][1]=xc.y; xv[j][2]=xc.z; xv[j][3]=xc.w;
            mv[j][0]=mc.x; mv[j][1]=mc.y; mv[j][2]=mc.z; mv[j][3]=mc.w;
        }
        #pragma unroll
        for (int i=0;i<4;i++){
            float p0,p1,p2,p3;
            unpack2(acc[i][0], p0, p1);
            unpack2(acc[i][1], p2, p3);
            p0 += bgv.x; p1 += bgv.y; p2 += bgv.z; p3 += bgv.w;
            float g0 = 1.f/(1.f+__expf(-p0));
            float g1 = 1.f/(1.f+__expf(-p1));
            float g2 = 1.f/(1.f+__expf(-p2));
            float g3 = 1.f/(1.f+__expf(-p3));
            float4 ov;
            ov.x = xv[0][i] + g0*mv[0][i];
            ov.y = xv[1][i] + g1*mv[1][i];
            ov.z = xv[2][i] + g2*mv[2][i];
            ov.w = xv[3][i] + g3*mv[3][i];
            *(float4*)(out_enh + (size_t)(rowbase + r0 + i)*Dq + e0) = ov;
        }
    }
}

extern "C" void kernel_launch(void* const* d_in, const int* in_sizes, int n_in,
                              void* d_out, int out_size)
{
    const float* x    = (const float*)d_in[0];
    const float* memv = (const float*)d_in[1];
    const float* wg   = (const float*)d_in[2];
    const float* bg   = (const float*)d_in[3];

    float* out_enh = (float*)d_out;                       // (B,S,D) first
    float* out_w   = out_enh + (size_t)NROWS * Dq;        // then (B,S,M)

    const size_t smem_bytes = (size_t)SMEM_FLOATS * sizeof(float);  // ~144 KB
    cudaFuncSetAttribute(vm_fused, cudaFuncAttributeMaxDynamicSharedMemorySize, (int)smem_bytes);

    vm_prep<<<(Mq*Dq + 255)/256, 256>>>(memv, wg);
    vm_fused<<<NROWS/RB, NT, smem_bytes>>>(x, memv, bg, out_enh, out_w);
}

// round 6
// speedup vs baseline: 1.1178x; 1.1157x over previous
#include <cuda_runtime.h>
#include <math.h>

#define Dq 256
#define Mq 512
#define RB 32
#define NT 512
#define NROWS (32*4096)

// SMEM float offsets
#define XS_OFF   0                        // xsT [256][32]  k-major
#define WS_OFF   (XS_OFF + Dq*RB)         // wsT [512][36]  logits/weights (group0 partial)
#define MS_OFF   (WS_OFF + Mq*36)         // msT [256][36]  memory_read
#define PS_OFF   (MS_OFF + Dq*36)         // PS  [512][36]  partial-sum scratch
#define R1_OFF   (PS_OFF + Mq*36)
#define R2_OFF   (R1_OFF + 512)
#define SMEM_FLOATS (R2_OFF + 512)        // 55296 floats = 216 KB

__device__ float g_memT[Dq*Mq];   // [k][m]  = memory[m][k]
__device__ float g_WgT[2*Dq*Dq];  // [dc][e] = Wg[e][dc]

typedef unsigned long long u64;

__device__ __forceinline__ u64 bcast2(float v){
    u64 r; asm("mov.b64 %0, {%1, %1};" : "=l"(r) : "f"(v)); return r;
}
__device__ __forceinline__ void unpack2(u64 v, float& lo, float& hi){
    asm("mov.b64 {%0, %1}, %2;" : "=f"(lo), "=f"(hi) : "l"(v));
}
__device__ __forceinline__ void ffma2(u64& d, u64 a, u64 b){
    asm("fma.rn.f32x2 %0, %1, %2, %0;" : "+l"(d) : "l"(a), "l"(b));
}
__device__ __forceinline__ float sigmoidf_(float p){
    return 1.f/(1.f+__expf(-p));
}

__global__ void vm_prep(const float* __restrict__ mem, const float* __restrict__ wg){
    int idx = blockIdx.x*blockDim.x + threadIdx.x;
    if (idx < Mq*Dq){
        int m = idx >> 8, k = idx & 255;      // memory: [512][256]
        g_memT[k*Mq + m] = mem[idx];
        int e = idx >> 9, dc = idx & 511;     // Wg: [256][512]
        g_WgT[dc*Dq + e] = wg[idx];
    }
}

__global__ __launch_bounds__(NT, 1)
void vm_fused(const float* __restrict__ x,
              const float* __restrict__ memv,
              const float* __restrict__ bg,
              float* __restrict__ out_enh,
              float* __restrict__ out_w)
{
    extern __shared__ float smem[];
    float* xsT  = smem + XS_OFF;   // [k][32]
    float* wsT  = smem + WS_OFF;   // [k][36]
    float* msT  = smem + MS_OFF;   // [k][36]
    float* PS   = smem + PS_OFF;   // [k][36]
    float* red1 = smem + R1_OFF;
    float* red2 = smem + R2_OFF;

    const int tid = threadIdx.x;
    const int rowbase = blockIdx.x * RB;
    const int wid = tid >> 5, lane = tid & 31;

    const int kh = wid >> 3;           // 0/1 : k-split group
    const int wc = wid & 7;            // col-block within group
    const int row_g = lane >> 3;       // 0..3
    const int col_o = lane & 7;        // 0..7
    const int r0 = row_g * 8;          // 8 rows per lane

    // ---------------- Phase A: x block -> xsT[k][r] (k-major) --------------
    {
        int r = lane;
        #pragma unroll
        for (int cc = 0; cc < 4; cc++){
            int c4 = wid + cc*16;
            float4 v = *(const float4*)(x + (size_t)(rowbase + r)*Dq + c4*4);
            xsT[(c4*4+0)*RB + r] = v.x;
            xsT[(c4*4+1)*RB + r] = v.y;
            xsT[(c4*4+2)*RB + r] = v.z;
            xsT[(c4*4+3)*RB + r] = v.w;
        }
    }
    __syncthreads();

    // ---------------- Phase B: logits = x @ memory^T  (k-split) ------------
    // group kh handles k in [kh*128, kh*128+128). warp: 32 rows x 64 cols.
    // lane: 8 rows x 8 cols (two 4-col strips). group0 -> wsT, group1 -> PS.
    {
        const int c0 = wc*64 + col_o*4;
        const int c1 = c0 + 32;
        const int kb = kh * 128;
        u64 acc[8][4];
        #pragma unroll
        for (int i=0;i<8;i++){ acc[i][0]=0; acc[i][1]=0; acc[i][2]=0; acc[i][3]=0; }

        #pragma unroll 4
        for (int k=0;k<128;k++){
            const int kk = kb + k;
            float4 av0 = *(const float4*)(xsT + kk*RB + r0);
            float4 av1 = *(const float4*)(xsT + kk*RB + r0 + 4);
            ulonglong2 B0 = *(const ulonglong2*)(g_memT + kk*Mq + c0);
            ulonglong2 B1 = *(const ulonglong2*)(g_memT + kk*Mq + c1);
            u64 a;
            a = bcast2(av0.x); ffma2(acc[0][0],a,B0.x); ffma2(acc[0][1],a,B0.y); ffma2(acc[0][2],a,B1.x); ffma2(acc[0][3],a,B1.y);
            a = bcast2(av0.y); ffma2(acc[1][0],a,B0.x); ffma2(acc[1][1],a,B0.y); ffma2(acc[1][2],a,B1.x); ffma2(acc[1][3],a,B1.y);
            a = bcast2(av0.z); ffma2(acc[2][0],a,B0.x); ffma2(acc[2][1],a,B0.y); ffma2(acc[2][2],a,B1.x); ffma2(acc[2][3],a,B1.y);
            a = bcast2(av0.w); ffma2(acc[3][0],a,B0.x); ffma2(acc[3][1],a,B0.y); ffma2(acc[3][2],a,B1.x); ffma2(acc[3][3],a,B1.y);
            a = bcast2(av1.x); ffma2(acc[4][0],a,B0.x); ffma2(acc[4][1],a,B0.y); ffma2(acc[4][2],a,B1.x); ffma2(acc[4][3],a,B1.y);
            a = bcast2(av1.y); ffma2(acc[5][0],a,B0.x); ffma2(acc[5][1],a,B0.y); ffma2(acc[5][2],a,B1.x); ffma2(acc[5][3],a,B1.y);
            a = bcast2(av1.z); ffma2(acc[6][0],a,B0.x); ffma2(acc[6][1],a,B0.y); ffma2(acc[6][2],a,B1.x); ffma2(acc[6][3],a,B1.y);
            a = bcast2(av1.w); ffma2(acc[7][0],a,B0.x); ffma2(acc[7][1],a,B0.y); ffma2(acc[7][2],a,B1.x); ffma2(acc[7][3],a,B1.y);
        }

        float* dst = (kh == 0) ? wsT : PS;
        #pragma unroll
        for (int half=0; half<2; half++){
            float t[4][8];
            #pragma unroll
            for (int i=0;i<4;i++){
                int ii = half*4 + i;
                unpack2(acc[ii][0], t[i][0], t[i][1]);
                unpack2(acc[ii][1], t[i][2], t[i][3]);
                unpack2(acc[ii][2], t[i][4], t[i][5]);
                unpack2(acc[ii][3], t[i][6], t[i][7]);
            }
            #pragma unroll
            for (int cc=0; cc<8; cc++){
                int col = (cc<4) ? (c0+cc) : (c1+cc-4);
                float4 v; v.x=t[0][cc]; v.y=t[1][cc]; v.z=t[2][cc]; v.w=t[3][cc];
                *(float4*)(dst + col*36 + r0 + half*4) = v;
            }
        }
    }
    __syncthreads();

    // ---------------- Phase C: reduce partials + softmax -------------------
    // warp w owns k-block [w*32, w*32+32); lane = row.
    {
        const int k0 = wid*32;
        float v[32];
        float mx = -3.402823466e38f;
        #pragma unroll
        for (int j=0;j<32;j++){
            v[j] = wsT[(k0+j)*36 + lane] + PS[(k0+j)*36 + lane];
            mx = fmaxf(mx, v[j]);
        }
        red1[wid*32 + lane] = mx;
        __syncthreads();
        float rm = -3.402823466e38f;
        #pragma unroll
        for (int i=0;i<16;i++) rm = fmaxf(rm, red1[i*32 + lane]);
        float sm = 0.f;
        #pragma unroll
        for (int j=0;j<32;j++){ v[j] = __expf(v[j]-rm); sm += v[j]; }
        red2[wid*32 + lane] = sm;
        __syncthreads();
        float rs = 0.f;
        #pragma unroll
        for (int i=0;i<16;i++) rs += red2[i*32 + lane];
        float inv = 1.f / rs;
        #pragma unroll
        for (int j=0;j<32;j++) wsT[(k0+j)*36 + lane] = v[j]*inv;
        __syncthreads();
        // coalesced out_w writeout (warp = 2 rows)
        #pragma unroll
        for (int rr=0; rr<2; rr++){
            int r = wid*2 + rr;
            float* wout = out_w + (size_t)(rowbase + r)*Mq;
            #pragma unroll
            for (int t=0;t<16;t++)
                wout[lane + 32*t] = wsT[(lane + 32*t)*36 + r];
        }
    }

    // ---------------- Phase D: mr = w @ memory  (k-split, K=512) -----------
    // group kh: k in [kh*256, +256). warp: 32 rows x 32 cols, lane 8x4.
    {
        const int c0 = wc*32 + col_o*4;
        const int kb = kh * 256;
        u64 acc[8][2];
        #pragma unroll
        for (int i=0;i<8;i++){ acc[i][0]=0; acc[i][1]=0; }
        #pragma unroll 4
        for (int k=0;k<256;k++){
            const int kk = kb + k;
            float4 av0 = *(const float4*)(wsT + kk*36 + r0);
            float4 av1 = *(const float4*)(wsT + kk*36 + r0 + 4);
            ulonglong2 Bv = *(const ulonglong2*)(memv + kk*Dq + c0);
            u64 a;
            a = bcast2(av0.x); ffma2(acc[0][0],a,Bv.x); ffma2(acc[0][1],a,Bv.y);
            a = bcast2(av0.y); ffma2(acc[1][0],a,Bv.x); ffma2(acc[1][1],a,Bv.y);
            a = bcast2(av0.z); ffma2(acc[2][0],a,Bv.x); ffma2(acc[2][1],a,Bv.y);
            a = bcast2(av0.w); ffma2(acc[3][0],a,Bv.x); ffma2(acc[3][1],a,Bv.y);
            a = bcast2(av1.x); ffma2(acc[4][0],a,Bv.x); ffma2(acc[4][1],a,Bv.y);
            a = bcast2(av1.y); ffma2(acc[5][0],a,Bv.x); ffma2(acc[5][1],a,Bv.y);
            a = bcast2(av1.z); ffma2(acc[6][0],a,Bv.x); ffma2(acc[6][1],a,Bv.y);
            a = bcast2(av1.w); ffma2(acc[7][0],a,Bv.x); ffma2(acc[7][1],a,Bv.y);
        }
        float* dst = (kh == 0) ? msT : PS;
        #pragma unroll
        for (int half=0; half<2; half++){
            float t[4][4];
            #pragma unroll
            for (int i=0;i<4;i++){
                int ii = half*4 + i;
                unpack2(acc[ii][0], t[i][0], t[i][1]);
                unpack2(acc[ii][1], t[i][2], t[i][3]);
            }
            #pragma unroll
            for (int cc=0; cc<4; cc++){
                float4 v; v.x=t[0][cc]; v.y=t[1][cc]; v.z=t[2][cc]; v.w=t[3][cc];
                *(float4*)(msT == dst ? (msT + (c0+cc)*36 + r0 + half*4)
                                      : (PS  + (c0+cc)*36 + r0 + half*4)) = v;
            }
        }
    }
    __syncthreads();
    // reduce PS into msT: 256 cols x 32 rows
    {
        #pragma unroll
        for (int t=0;t<16;t++){
            int idx = tid + t*512;          // 0..8191
            int col = idx >> 5, row = idx & 31;
            msT[col*36 + row] += PS[col*36 + row];
        }
    }
    __syncthreads();

    // ---------------- Phase E: gate GEMMs (group0: W1.x, group1: W2.mr) ----
    {
        const int e0 = wc*32 + col_o*4;
        u64 acc[8][2];
        #pragma unroll
        for (int i=0;i<8;i++){ acc[i][0]=0; acc[i][1]=0; }

        if (kh == 0){
            #pragma unroll 4
            for (int k=0;k<256;k++){
                float4 av0 = *(const float4*)(xsT + k*RB + r0);
                float4 av1 = *(const float4*)(xsT + k*RB + r0 + 4);
                ulonglong2 Bv = *(const ulonglong2*)(g_WgT + (size_t)k*Dq + e0);
                u64 a;
                a = bcast2(av0.x); ffma2(acc[0][0],a,Bv.x); ffma2(acc[0][1],a,Bv.y);
                a = bcast2(av0.y); ffma2(acc[1][0],a,Bv.x); ffma2(acc[1][1],a,Bv.y);
                a = bcast2(av0.z); ffma2(acc[2][0],a,Bv.x); ffma2(acc[2][1],a,Bv.y);
                a = bcast2(av0.w); ffma2(acc[3][0],a,Bv.x); ffma2(acc[3][1],a,Bv.y);
                a = bcast2(av1.x); ffma2(acc[4][0],a,Bv.x); ffma2(acc[4][1],a,Bv.y);
                a = bcast2(av1.y); ffma2(acc[5][0],a,Bv.x); ffma2(acc[5][1],a,Bv.y);
                a = bcast2(av1.z); ffma2(acc[6][0],a,Bv.x); ffma2(acc[6][1],a,Bv.y);
                a = bcast2(av1.w); ffma2(acc[7][0],a,Bv.x); ffma2(acc[7][1],a,Bv.y);
            }
            // store partial z1 to PS
            #pragma unroll
            for (int half=0; half<2; half++){
                float t[4][4];
                #pragma unroll
                for (int i=0;i<4;i++){
                    int ii = half*4 + i;
                    unpack2(acc[ii][0], t[i][0], t[i][1]);
                    unpack2(acc[ii][1], t[i][2], t[i][3]);
                }
                #pragma unroll
                for (int cc=0; cc<4; cc++){
                    float4 v; v.x=t[0][cc]; v.y=t[1][cc]; v.z=t[2][cc]; v.w=t[3][cc];
                    *(float4*)(PS + (e0+cc)*36 + r0 + half*4) = v;
                }
            }
            __syncthreads();
            // group0 idle in epilogue (cheap)
        } else {
            #pragma unroll 4
            for (int k=0;k<256;k++){
                float4 av0 = *(const float4*)(msT + k*36 + r0);
                float4 av1 = *(const float4*)(msT + k*36 + r0 + 4);
                ulonglong2 Bv = *(const ulonglong2*)(g_WgT + (size_t)(Dq+k)*Dq + e0);
                u64 a;
                a = bcast2(av0.x); ffma2(acc[0][0],a,Bv.x); ffma2(acc[0][1],a,Bv.y);
                a = bcast2(av0.y); ffma2(acc[1][0],a,Bv.x); ffma2(acc[1][1],a,Bv.y);
                a = bcast2(av0.z); ffma2(acc[2][0],a,Bv.x); ffma2(acc[2][1],a,Bv.y);
                a = bcast2(av0.w); ffma2(acc[3][0],a,Bv.x); ffma2(acc[3][1],a,Bv.y);
                a = bcast2(av1.x); ffma2(acc[4][0],a,Bv.x); ffma2(acc[4][1],a,Bv.y);
                a = bcast2(av1.y); ffma2(acc[5][0],a,Bv.x); ffma2(acc[5][1],a,Bv.y);
                a = bcast2(av1.z); ffma2(acc[6][0],a,Bv.x); ffma2(acc[6][1],a,Bv.y);
                a = bcast2(av1.w); ffma2(acc[7][0],a,Bv.x); ffma2(acc[7][1],a,Bv.y);
            }
            __syncthreads();   // wait for group0's PS partial

            // epilogue: z = z1(PS) + z2(acc) + bg ; g = sigmoid ; out = x + g*mr
            float z[8][4];
            #pragma unroll
            for (int i=0;i<8;i++){
                unpack2(acc[i][0], z[i][0], z[i][1]);
                unpack2(acc[i][1], z[i][2], z[i][3]);
            }
            float4 bgv = *(const float4*)(bg + e0);
            float ob[8][4];
            #pragma unroll
            for (int j=0;j<4;j++){
                int e = e0 + j;
                float bj = (j==0?bgv.x : j==1?bgv.y : j==2?bgv.z : bgv.w);
                float4 p0 = *(const float4*)(PS  + e*36 + r0);
                float4 p1 = *(const float4*)(PS  + e*36 + r0 + 4);
                float4 m0 = *(const float4*)(msT + e*36 + r0);
                float4 m1 = *(const float4*)(msT + e*36 + r0 + 4);
                float4 x0 = *(const float4*)(xsT + e*RB + r0);
                float4 x1 = *(const float4*)(xsT + e*RB + r0 + 4);
                ob[0][j] = x0.x + sigmoidf_(z[0][j] + p0.x + bj) * m0.x;
                ob[1][j] = x0.y + sigmoidf_(z[1][j] + p0.y + bj) * m0.y;
                ob[2][j] = x0.z + sigmoidf_(z[2][j] + p0.z + bj) * m0.z;
                ob[3][j] = x0.w + sigmoidf_(z[3][j] + p0.w + bj) * m0.w;
                ob[4][j] = x1.x + sigmoidf_(z[4][j] + p1.x + bj) * m1.x;
                ob[5][j] = x1.y + sigmoidf_(z[5][j] + p1.y + bj) * m1.y;
                ob[6][j] = x1.z + sigmoidf_(z[6][j] + p1.z + bj) * m1.z;
                ob[7][j] = x1.w + sigmoidf_(z[7][j] + p1.w + bj) * m1.w;
            }
            #pragma unroll
            for (int i=0;i<8;i++){
                float4 v; v.x=ob[i][0]; v.y=ob[i][1]; v.z=ob[i][2]; v.w=ob[i][3];
                *(float4*)(out_enh + (size_t)(rowbase + r0 + i)*Dq + e0) = v;
            }
        }
    }
}

extern "C" void kernel_launch(void* const* d_in, const int* in_sizes, int n_in,
                              void* d_out, int out_size)
{
    const float* x    = (const float*)d_in[0];
    const float* memv = (const float*)d_in[1];
    const float* wg   = (const float*)d_in[2];
    const float* bg   = (const float*)d_in[3];

    float* out_enh = (float*)d_out;                       // (B,S,D) first
    float* out_w   = out_enh + (size_t)NROWS * Dq;        // then (B,S,M)

    const size_t smem_bytes = (size_t)SMEM_FLOATS * sizeof(float);  // 216 KB
    cudaFuncSetAttribute(vm_fused, cudaFuncAttributeMaxDynamicSharedMemorySize, (int)smem_bytes);

    vm_prep<<<(Mq*Dq + 255)/256, 256>>>(memv, wg);
    vm_fused<<<NROWS/RB, NT, smem_bytes>>>(x, memv, bg, out_enh, out_w);
}